// round 1
// baseline (speedup 1.0000x reference)
#include <cuda_runtime.h>
#include <cuda_bf16.h>

// GraphConv: supports = wv @ W.T + b; agg = einsum(mask, supports[neighs]) + supports[src];
//            out = supports with out[src] += leakyrelu(agg, 0.2)
// Shapes (fixed problem): N=100000, S=50000, K=16, DIN=DOUT=256, fp32.

#define DIN  256
#define DOUT 256
#define BM 128
#define BN 128
#define BK 16

// Original (pre-update) supports. Needed because neighbors must read the
// pre-scatter values while src rows in d_out get overwritten.
__device__ float g_scratch[100000 * 256];

// ---------------------------------------------------------------------------
// Kernel 1: C = A @ W^T + b, written to BOTH d_out and g_scratch.
// Classic 128x128x16 shared-memory SGEMM, 256 threads, 8x8 per thread.
// ---------------------------------------------------------------------------
__global__ __launch_bounds__(256) void gemm_kernel(
    const float* __restrict__ A,      // [N, DIN]
    const float* __restrict__ W,      // [DOUT, DIN]
    const float* __restrict__ bias,   // [DOUT]
    float* __restrict__ C,            // [N, DOUT] = d_out
    int N)
{
    __shared__ float As[BK][BM];
    __shared__ float Ws[BK][BN];

    const int bm  = blockIdx.x * BM;
    const int bn  = blockIdx.y * BN;
    const int tid = threadIdx.x;
    const int tx  = tid & 15;        // 0..15  (n direction)
    const int ty  = tid >> 4;        // 0..15  (m direction)
    const int lr  = tid >> 2;        // 0..63  (load row)
    const int lc  = (tid & 3) * 4;   // 0,4,8,12 (load col, float4)

    float acc[8][8] = {};

    for (int k0 = 0; k0 < DIN; k0 += BK) {
        #pragma unroll
        for (int h = 0; h < 2; h++) {
            int r  = lr + h * 64;
            int gm = bm + r;
            float4 v = make_float4(0.f, 0.f, 0.f, 0.f);
            if (gm < N)
                v = *reinterpret_cast<const float4*>(&A[(long long)gm * DIN + k0 + lc]);
            As[lc + 0][r] = v.x; As[lc + 1][r] = v.y;
            As[lc + 2][r] = v.z; As[lc + 3][r] = v.w;

            int gn = bn + r;  // < DOUT always (gridDim.y * BN == DOUT)
            float4 w = *reinterpret_cast<const float4*>(&W[(long long)gn * DIN + k0 + lc]);
            Ws[lc + 0][r] = w.x; Ws[lc + 1][r] = w.y;
            Ws[lc + 2][r] = w.z; Ws[lc + 3][r] = w.w;
        }
        __syncthreads();

        #pragma unroll
        for (int k = 0; k < BK; k++) {
            float af[8], wf[8];
            #pragma unroll
            for (int i = 0; i < 8; i++) af[i] = As[k][ty * 8 + i];
            #pragma unroll
            for (int j = 0; j < 8; j++) wf[j] = Ws[k][tx * 8 + j];
            #pragma unroll
            for (int i = 0; i < 8; i++)
                #pragma unroll
                for (int j = 0; j < 8; j++)
                    acc[i][j] += af[i] * wf[j];
        }
        __syncthreads();
    }

    float bb[8];
    #pragma unroll
    for (int j = 0; j < 8; j++) bb[j] = bias[bn + tx * 8 + j];

    #pragma unroll
    for (int i = 0; i < 8; i++) {
        int gm = bm + ty * 8 + i;
        if (gm >= N) continue;
        #pragma unroll
        for (int j = 0; j < 8; j += 4) {
            float4 v;
            v.x = acc[i][j + 0] + bb[j + 0];
            v.y = acc[i][j + 1] + bb[j + 1];
            v.z = acc[i][j + 2] + bb[j + 2];
            v.w = acc[i][j + 3] + bb[j + 3];
            long long off = (long long)gm * DOUT + bn + tx * 8 + j;
            *reinterpret_cast<float4*>(&C[off])         = v;
            *reinterpret_cast<float4*>(&g_scratch[off]) = v;
        }
    }
}

// ---------------------------------------------------------------------------
// Index loader robust to int64-vs-int32 storage (JAX x64 may be disabled).
// ---------------------------------------------------------------------------
__device__ __forceinline__ long long load_index(const void* p, long long i, bool is64)
{
    if (is64) return reinterpret_cast<const long long*>(p)[i];
    return (long long)reinterpret_cast<const int*>(p)[i];
}

// ---------------------------------------------------------------------------
// Kernel 2: per-src aggregation + leaky-relu + in-place add, reading ONLY the
// pre-update copy in g_scratch, writing the updated rows into d_out.
// 64 threads (x float4) cover a 256-float row; 4 src nodes per 256-thread block.
// ---------------------------------------------------------------------------
__global__ __launch_bounds__(256) void agg_kernel(
    const void* __restrict__ src_idx,
    const void* __restrict__ neighs,
    const float* __restrict__ mask,   // [S, K]
    float* __restrict__ out,          // [N, DOUT] = d_out
    int S, int K)
{
    const int s    = blockIdx.x * 4 + (threadIdx.x >> 6);
    const int lane = threadIdx.x & 63;
    if (s >= S) return;

    // dtype sniff: if the underlying data is int64, the high words of the
    // first elements are all zero (indices < 2^31). If it is int32, those
    // words are random indices in [0, N) -> virtually never all zero.
    const int* ni = reinterpret_cast<const int*>(neighs);
    const bool is64 = ((ni[1] | ni[3] | ni[5] | ni[7]) == 0);

    const long long src = load_index(src_idx, s, is64);
    const float4* ob = reinterpret_cast<const float4*>(g_scratch);

    float4 sv  = ob[src * 64 + lane];
    float4 acc = make_float4(0.f, 0.f, 0.f, 0.f);

    if (K == 16) {
        long long nn[16];
        float     mm[16];
        #pragma unroll
        for (int k = 0; k < 16; k++) {
            nn[k] = load_index(neighs, (long long)s * 16 + k, is64);
            mm[k] = mask[s * 16 + k];
        }
        #pragma unroll
        for (int k = 0; k < 16; k++) {
            float4 nv = ob[nn[k] * 64 + lane];
            acc.x += mm[k] * nv.x;
            acc.y += mm[k] * nv.y;
            acc.z += mm[k] * nv.z;
            acc.w += mm[k] * nv.w;
        }
    } else {
        for (int k = 0; k < K; k++) {
            long long n  = load_index(neighs, (long long)s * K + k, is64);
            float     mk = mask[s * K + k];
            float4 nv = ob[n * 64 + lane];
            acc.x += mk * nv.x;
            acc.y += mk * nv.y;
            acc.z += mk * nv.z;
            acc.w += mk * nv.w;
        }
    }

    float4 t;
    t.x = acc.x + sv.x; t.y = acc.y + sv.y;
    t.z = acc.z + sv.z; t.w = acc.w + sv.w;
    t.x = (t.x >= 0.f) ? t.x : 0.2f * t.x;
    t.y = (t.y >= 0.f) ? t.y : 0.2f * t.y;
    t.z = (t.z >= 0.f) ? t.z : 0.2f * t.z;
    t.w = (t.w >= 0.f) ? t.w : 0.2f * t.w;

    float4 o;
    o.x = sv.x + t.x; o.y = sv.y + t.y;
    o.z = sv.z + t.z; o.w = sv.w + t.w;

    reinterpret_cast<float4*>(out)[src * 64 + lane] = o;
}

// ---------------------------------------------------------------------------
// Launch: inputs in metadata order:
//   0 word_vectors [N,DIN] f32, 1 src_idx [S] int, 2 neighs_idx [S,K] int,
//   3 src_mask [S,K] f32, 4 W [DOUT,DIN] f32, 5 b [DOUT] f32
// ---------------------------------------------------------------------------
extern "C" void kernel_launch(void* const* d_in, const int* in_sizes, int n_in,
                              void* d_out, int out_size)
{
    const float* wv    = (const float*)d_in[0];
    const void*  srcix = d_in[1];
    const void*  neigh = d_in[2];
    const float* mask  = (const float*)d_in[3];
    const float* W     = (const float*)d_in[4];
    const float* bias  = (const float*)d_in[5];
    float*       out   = (float*)d_out;

    const int dout = in_sizes[5];          // 256
    const int din  = in_sizes[4] / dout;   // 256
    const int N    = in_sizes[0] / din;    // 100000
    const int S    = in_sizes[1];          // 50000
    const int K    = in_sizes[3] / S;      // 16
    (void)n_in; (void)out_size;

    dim3 ggrid((N + BM - 1) / BM, DOUT / BN);
    gemm_kernel<<<ggrid, 256>>>(wv, W, bias, out, N);

    agg_kernel<<<(S + 3) / 4, 256>>>(srcix, neigh, mask, out, S, K);
}

// round 3
// speedup vs baseline: 2.0579x; 2.0579x over previous
#include <cuda_runtime.h>
#include <cuda_bf16.h>

// GraphConv: supports = wv @ W.T + b; agg = einsum(mask, supports[neighs]) + supports[src];
//            out = supports with out[src] += leakyrelu(agg, 0.2)
// N=100000, S=50000, K=16, DIN=DOUT=256, fp32.
// GEMM uses TF32 mma.sync (m16n8k8) tensor cores.

#define DIN  256
#define DOUT 256
#define BM 128
#define BN 128
#define PITCH 36   // smem row pitch in floats: bank = (36r+c)%32 = 4r+c -> conflict-free frags

// Pre-update supports copy (neighbors must read pre-scatter values).
__device__ float g_scratch[100000 * 256];

// cvt.rna.tf32.f32 produces a .b32 bit-pattern -> "=r" destination.
__device__ __forceinline__ unsigned to_tf32(float x) {
    unsigned u;
    asm("cvt.rna.tf32.f32 %0, %1;" : "=r"(u) : "f"(x));
    return u;
}

__device__ __forceinline__ void mma_tf32(float* d, const unsigned* a, const unsigned* b) {
    asm volatile(
        "mma.sync.aligned.m16n8k8.row.col.f32.tf32.tf32.f32 "
        "{%0,%1,%2,%3}, {%4,%5,%6,%7}, {%8,%9}, {%0,%1,%2,%3};"
        : "+f"(d[0]), "+f"(d[1]), "+f"(d[2]), "+f"(d[3])
        : "r"(a[0]), "r"(a[1]), "r"(a[2]), "r"(a[3]), "r"(b[0]), "r"(b[1]));
}

// ---------------------------------------------------------------------------
// Kernel 1: C = A @ W^T + b  (TF32 tensor cores), written to d_out AND scratch.
// Block 128x128, 8 warps (4m x 2n), warp tile 32x64, k-tile 32 (4 x k8).
// Register prefetch of next k-tile overlaps global latency with HMMA compute.
// ---------------------------------------------------------------------------
__global__ __launch_bounds__(256) void gemm_tc(
    const float* __restrict__ A,      // [N, DIN]
    const float* __restrict__ W,      // [DOUT, DIN]
    const float* __restrict__ bias,   // [DOUT]
    float* __restrict__ C,            // [N, DOUT]
    int N)
{
    __shared__ float As[128 * PITCH];
    __shared__ float Ws[128 * PITCH];

    const int tid  = threadIdx.x;
    const int bm   = blockIdx.x * BM;
    const int bn   = blockIdx.y * BN;
    const int lr   = tid >> 3;          // 0..31 load row within quarter
    const int lc4  = (tid & 7) * 4;     // 0,4,...,28 load col (float4)
    const int warp = tid >> 5;
    const int lane = tid & 31;
    const int wm   = (warp & 3) * 32;
    const int wn   = (warp >> 2) * 64;
    const int grp  = lane >> 2;         // 0..7
    const int qd   = lane & 3;          // 0..3

    float4 pa[4], pw[4];
    const float4 z4 = make_float4(0.f, 0.f, 0.f, 0.f);

    // prefetch k-tile 0
    #pragma unroll
    for (int i = 0; i < 4; i++) {
        int row = lr + i * 32;
        int gm  = bm + row;
        pa[i] = (gm < N) ? *reinterpret_cast<const float4*>(A + (size_t)gm * DIN + lc4) : z4;
        pw[i] = *reinterpret_cast<const float4*>(W + (size_t)(bn + row) * DIN + lc4);
    }

    float acc[2][8][4] = {};

    #pragma unroll 1
    for (int it = 0; it < DIN / 32; ++it) {
        // stage prefetched tile into smem (convert to tf32 once here)
        #pragma unroll
        for (int i = 0; i < 4; i++) {
            int row = lr + i * 32;
            float* pA = &As[row * PITCH + lc4];
            pA[0] = __uint_as_float(to_tf32(pa[i].x));
            pA[1] = __uint_as_float(to_tf32(pa[i].y));
            pA[2] = __uint_as_float(to_tf32(pa[i].z));
            pA[3] = __uint_as_float(to_tf32(pa[i].w));
            float* pW = &Ws[row * PITCH + lc4];
            pW[0] = __uint_as_float(to_tf32(pw[i].x));
            pW[1] = __uint_as_float(to_tf32(pw[i].y));
            pW[2] = __uint_as_float(to_tf32(pw[i].z));
            pW[3] = __uint_as_float(to_tf32(pw[i].w));
        }
        __syncthreads();

        // prefetch next k-tile while HMMAs run
        if (it + 1 < DIN / 32) {
            int k0 = (it + 1) * 32;
            #pragma unroll
            for (int i = 0; i < 4; i++) {
                int row = lr + i * 32;
                int gm  = bm + row;
                pa[i] = (gm < N) ? *reinterpret_cast<const float4*>(A + (size_t)gm * DIN + k0 + lc4) : z4;
                pw[i] = *reinterpret_cast<const float4*>(W + (size_t)(bn + row) * DIN + k0 + lc4);
            }
        }

        #pragma unroll
        for (int ks = 0; ks < 4; ++ks) {
            const int k = ks * 8;
            unsigned af[2][4], bf[8][2];
            #pragma unroll
            for (int i = 0; i < 2; i++) {
                int r = wm + i * 16 + grp;
                af[i][0] = __float_as_uint(As[r * PITCH + k + qd]);
                af[i][1] = __float_as_uint(As[(r + 8) * PITCH + k + qd]);
                af[i][2] = __float_as_uint(As[r * PITCH + k + qd + 4]);
                af[i][3] = __float_as_uint(As[(r + 8) * PITCH + k + qd + 4]);
            }
            #pragma unroll
            for (int j = 0; j < 8; j++) {
                int n = wn + j * 8 + grp;
                bf[j][0] = __float_as_uint(Ws[n * PITCH + k + qd]);
                bf[j][1] = __float_as_uint(Ws[n * PITCH + k + qd + 4]);
            }
            #pragma unroll
            for (int i = 0; i < 2; i++)
                #pragma unroll
                for (int j = 0; j < 8; j++)
                    mma_tf32(acc[i][j], af[i], bf[j]);
        }
        __syncthreads();
    }

    // epilogue: + bias, write to both C and g_scratch
    #pragma unroll
    for (int i = 0; i < 2; i++) {
        int r0 = bm + wm + i * 16 + grp;
        #pragma unroll
        for (int j = 0; j < 8; j++) {
            int col = bn + wn + j * 8 + 2 * qd;
            float b0 = bias[col], b1 = bias[col + 1];
            if (r0 < N) {
                float2 v = make_float2(acc[i][j][0] + b0, acc[i][j][1] + b1);
                size_t off = (size_t)r0 * DOUT + col;
                *reinterpret_cast<float2*>(C + off)         = v;
                *reinterpret_cast<float2*>(g_scratch + off) = v;
            }
            int r1 = r0 + 8;
            if (r1 < N) {
                float2 v = make_float2(acc[i][j][2] + b0, acc[i][j][3] + b1);
                size_t off = (size_t)r1 * DOUT + col;
                *reinterpret_cast<float2*>(C + off)         = v;
                *reinterpret_cast<float2*>(g_scratch + off) = v;
            }
        }
    }
}

// ---------------------------------------------------------------------------
// Index loader robust to int64-vs-int32 storage.
// ---------------------------------------------------------------------------
__device__ __forceinline__ long long load_index(const void* p, long long i, bool is64)
{
    if (is64) return reinterpret_cast<const long long*>(p)[i];
    return (long long)reinterpret_cast<const int*>(p)[i];
}

// ---------------------------------------------------------------------------
// Kernel 2: aggregation + leakyrelu + in-place add. Reads pre-update copy in
// g_scratch, writes updated src rows into d_out.
// Indices/masks staged in smem (no per-thread index register arrays -> high occ).
// 4 src nodes per 256-thread block; 64 threads x float4 per row.
// ---------------------------------------------------------------------------
__global__ __launch_bounds__(256) void agg_kernel(
    const void* __restrict__ src_idx,
    const void* __restrict__ neighs,
    const float* __restrict__ mask,   // [S, K]
    float* __restrict__ out,          // [N, DOUT]
    int S, int K)
{
    __shared__ int   s_nn[4][16];
    __shared__ float s_mm[4][16];
    __shared__ int   s_src[4];

    const int grp  = threadIdx.x >> 6;   // 0..3 : which src in this block
    const int lane = threadIdx.x & 63;   // 0..63: float4 lane within row
    const int s    = blockIdx.x * 4 + grp;

    // dtype sniff: int64 data has zero high words for the first elements
    // (indices < 2^31); int32 data puts random indices there.
    const int* ni = reinterpret_cast<const int*>(neighs);
    const bool is64 = ((ni[1] | ni[3] | ni[5] | ni[7]) == 0);

    if (s < S) {
        if (lane < 16 && lane < K) {
            s_nn[grp][lane] = (int)load_index(neighs, (long long)s * K + lane, is64);
            s_mm[grp][lane] = mask[s * K + lane];
        }
        if (lane == 0)
            s_src[grp] = (int)load_index(src_idx, s, is64);
    }
    __syncthreads();
    if (s >= S) return;

    const float4* ob = reinterpret_cast<const float4*>(g_scratch);
    const int src = s_src[grp];

    float4 sv  = ob[(size_t)src * 64 + lane];
    float4 acc = make_float4(0.f, 0.f, 0.f, 0.f);

    if (K == 16) {
        #pragma unroll
        for (int k = 0; k < 16; k++) {
            const int   n = s_nn[grp][k];
            const float m = s_mm[grp][k];
            float4 nv = ob[(size_t)n * 64 + lane];
            acc.x += m * nv.x; acc.y += m * nv.y;
            acc.z += m * nv.z; acc.w += m * nv.w;
        }
    } else {
        for (int k = 0; k < K; k++) {
            long long n = load_index(neighs, (long long)s * K + k, is64);
            float     m = mask[s * K + k];
            float4 nv = ob[(size_t)n * 64 + lane];
            acc.x += m * nv.x; acc.y += m * nv.y;
            acc.z += m * nv.z; acc.w += m * nv.w;
        }
    }

    float4 t;
    t.x = acc.x + sv.x; t.y = acc.y + sv.y;
    t.z = acc.z + sv.z; t.w = acc.w + sv.w;
    t.x = (t.x >= 0.f) ? t.x : 0.2f * t.x;
    t.y = (t.y >= 0.f) ? t.y : 0.2f * t.y;
    t.z = (t.z >= 0.f) ? t.z : 0.2f * t.z;
    t.w = (t.w >= 0.f) ? t.w : 0.2f * t.w;

    float4 o;
    o.x = sv.x + t.x; o.y = sv.y + t.y;
    o.z = sv.z + t.z; o.w = sv.w + t.w;

    reinterpret_cast<float4*>(out)[(size_t)src * 64 + lane] = o;
}

// ---------------------------------------------------------------------------
// Inputs (metadata order):
//   0 word_vectors [N,DIN] f32, 1 src_idx [S] int, 2 neighs_idx [S,K] int,
//   3 src_mask [S,K] f32, 4 W [DOUT,DIN] f32, 5 b [DOUT] f32
// ---------------------------------------------------------------------------
extern "C" void kernel_launch(void* const* d_in, const int* in_sizes, int n_in,
                              void* d_out, int out_size)
{
    const float* wv    = (const float*)d_in[0];
    const void*  srcix = d_in[1];
    const void*  neigh = d_in[2];
    const float* mask  = (const float*)d_in[3];
    const float* W     = (const float*)d_in[4];
    const float* bias  = (const float*)d_in[5];
    float*       out   = (float*)d_out;

    const int dout = in_sizes[5];          // 256
    const int din  = in_sizes[4] / dout;   // 256
    const int N    = in_sizes[0] / din;    // 100000
    const int S    = in_sizes[1];          // 50000
    const int K    = in_sizes[3] / S;      // 16
    (void)n_in; (void)out_size; (void)din;

    dim3 ggrid((N + BM - 1) / BM, DOUT / BN);
    gemm_tc<<<ggrid, 256>>>(wv, W, bias, out, N);

    agg_kernel<<<(S + 3) / 4, 256>>>(srcix, neigh, mask, out, S, K);
}

// round 4
// speedup vs baseline: 2.3277x; 1.1311x over previous
#include <cuda_runtime.h>
#include <cuda_fp16.h>
#include <cuda_bf16.h>

// GraphConv: supports = wv @ W.T + b; agg = einsum(mask, supports[neighs]) + supports[src];
//            out = supports with out[src] += leakyrelu(agg, 0.2)
// N=100000, S=50000, K=16, DIN=DOUT=256, fp32.
// GEMM: TF32 mma.sync with permuted-fragment smem (LDS.128 fragment loads).
// Aggregation: neighbors gathered from an fp16 copy of supports (halves traffic);
// src row read in fp32 from d_out (race-free: unique src rows).

#define DIN  256
#define DOUT 256
#define BM 128
#define BN 128

// fp16 pre-update supports (neighbor gather table), 51.2 MB.
__device__ __half g_scratch_h[100000 * 256];

__device__ __forceinline__ unsigned to_tf32(float x) {
    unsigned u;
    asm("cvt.rna.tf32.f32 %0, %1;" : "=r"(u) : "f"(x));
    return u;
}

__device__ __forceinline__ void mma_tf32(float* d, const unsigned* a, unsigned b0, unsigned b1) {
    asm volatile(
        "mma.sync.aligned.m16n8k8.row.col.f32.tf32.tf32.f32 "
        "{%0,%1,%2,%3}, {%4,%5,%6,%7}, {%8,%9}, {%0,%1,%2,%3};"
        : "+f"(d[0]), "+f"(d[1]), "+f"(d[2]), "+f"(d[3])
        : "r"(a[0]), "r"(a[1]), "r"(a[2]), "r"(a[3]), "r"(b0), "r"(b1));
}

// ---------------------------------------------------------------------------
// Kernel 1: C = A @ W^T + b (fp32 to d_out) and fp16 copy to g_scratch_h.
// Block 128x128, 8 warps (4m x 2n), warp tile 32x64, k-tile 32 = 4 x k8.
//
// Smem holds tiles in PERMUTED FRAGMENT ORDER:
//   A slot  [ks][t][g][qd^ks] (float4) = { A[16t+g][8ks+qd],  A[16t+g+8][8ks+qd],
//                                          A[16t+g][8ks+qd+4],A[16t+g+8][8ks+qd+4] }
//   W slot  [ks][jp][g][qd^ks](float4) = { W[16jp+g][8ks+qd],  W[16jp+g][8ks+qd+4],
//                                          W[16jp+8+g][8ks+qd],W[16jp+8+g][8ks+qd+4] }
// so a consumer thread fetches each fragment with a single conflict-free LDS.128.
// ---------------------------------------------------------------------------
__global__ __launch_bounds__(256) void gemm_tc(
    const float* __restrict__ A,      // [N, DIN]
    const float* __restrict__ W,      // [DOUT, DIN]
    const float* __restrict__ bias,   // [DOUT]
    float* __restrict__ C,            // [N, DOUT]
    int N)
{
    __shared__ float4 As[1024];   // 16 KB
    __shared__ float4 Ws[1024];   // 16 KB

    const int tid  = threadIdx.x;
    const int bm   = blockIdx.x * BM;
    const int bn   = blockIdx.y * BN;
    const int lr   = tid >> 3;          // 0..31 producer row within quarter
    const int lc4  = (tid & 7) * 4;     // 0,4,...,28 producer k (float4)
    const int warp = tid >> 5;
    const int lane = tid & 31;
    const int grp  = lane >> 2;         // 0..7
    const int qd   = lane & 3;          // 0..3
    const int t0   = (warp & 3) * 2;    // m16-tile base for this warp
    const int jpb  = (warp >> 2) * 4;   // jj-pair base for this warp
    const int wm   = (warp & 3) * 32;
    const int wn   = (warp >> 2) * 64;

    const int pks = lc4 >> 3;           // producer ks (0..3), const per thread
    const int ph  = (lc4 >> 2) & 1;     // producer k half (0/1)

    float4 pa[4], pw[4];
    const float4 z4 = make_float4(0.f, 0.f, 0.f, 0.f);

    // prefetch k-tile 0
    #pragma unroll
    for (int i = 0; i < 4; i++) {
        int row = lr + i * 32;
        int gm  = bm + row;
        pa[i] = (gm < N) ? *reinterpret_cast<const float4*>(A + (size_t)gm * DIN + lc4) : z4;
        pw[i] = *reinterpret_cast<const float4*>(W + (size_t)(bn + row) * DIN + lc4);
    }

    float acc[2][8][4] = {};

    #pragma unroll 1
    for (int it = 0; it < DIN / 32; ++it) {
        // stage prefetched tile into permuted smem (tf32-round here)
        #pragma unroll
        for (int i = 0; i < 4; i++) {
            const int r  = lr + i * 32;
            // A side: t = r>>4, g = r&7, p = (r>>3)&1
            {
                const int aslot = ((pks * 8 + (r >> 4)) * 8 + (r & 7)) * 4;
                const int e     = ((r >> 3) & 1) + 2 * ph;
                float* dst = reinterpret_cast<float*>(As);
                unsigned v0 = to_tf32(pa[i].x), v1 = to_tf32(pa[i].y);
                unsigned v2 = to_tf32(pa[i].z), v3 = to_tf32(pa[i].w);
                dst[(aslot + (0 ^ pks)) * 4 + e] = __uint_as_float(v0);
                dst[(aslot + (1 ^ pks)) * 4 + e] = __uint_as_float(v1);
                dst[(aslot + (2 ^ pks)) * 4 + e] = __uint_as_float(v2);
                dst[(aslot + (3 ^ pks)) * 4 + e] = __uint_as_float(v3);
            }
            // W side: jj = r>>3, g = r&7, jp = jj>>1, jo = jj&1
            {
                const int bslot = ((pks * 8 + (r >> 4)) * 8 + (r & 7)) * 4;  // jp = r>>4
                const int e     = ph + 2 * ((r >> 3) & 1);                   // jo = (r>>3)&1
                float* dst = reinterpret_cast<float*>(Ws);
                unsigned v0 = to_tf32(pw[i].x), v1 = to_tf32(pw[i].y);
                unsigned v2 = to_tf32(pw[i].z), v3 = to_tf32(pw[i].w);
                dst[(bslot + (0 ^ pks)) * 4 + e] = __uint_as_float(v0);
                dst[(bslot + (1 ^ pks)) * 4 + e] = __uint_as_float(v1);
                dst[(bslot + (2 ^ pks)) * 4 + e] = __uint_as_float(v2);
                dst[(bslot + (3 ^ pks)) * 4 + e] = __uint_as_float(v3);
            }
        }
        __syncthreads();

        // prefetch next k-tile while HMMAs run
        if (it + 1 < DIN / 32) {
            int k0 = (it + 1) * 32;
            #pragma unroll
            for (int i = 0; i < 4; i++) {
                int row = lr + i * 32;
                int gm  = bm + row;
                pa[i] = (gm < N) ? *reinterpret_cast<const float4*>(A + (size_t)gm * DIN + k0 + lc4) : z4;
                pw[i] = *reinterpret_cast<const float4*>(W + (size_t)(bn + row) * DIN + k0 + lc4);
            }
        }

        #pragma unroll
        for (int ks = 0; ks < 4; ++ks) {
            const int qsw = qd ^ ks;
            float4 a0 = As[((ks * 8 + t0 + 0) * 8 + grp) * 4 + qsw];
            float4 a1 = As[((ks * 8 + t0 + 1) * 8 + grp) * 4 + qsw];
            float4 bv[4];
            #pragma unroll
            for (int jp = 0; jp < 4; jp++)
                bv[jp] = Ws[((ks * 8 + jpb + jp) * 8 + grp) * 4 + qsw];

            unsigned af[2][4];
            af[0][0] = __float_as_uint(a0.x); af[0][1] = __float_as_uint(a0.y);
            af[0][2] = __float_as_uint(a0.z); af[0][3] = __float_as_uint(a0.w);
            af[1][0] = __float_as_uint(a1.x); af[1][1] = __float_as_uint(a1.y);
            af[1][2] = __float_as_uint(a1.z); af[1][3] = __float_as_uint(a1.w);

            #pragma unroll
            for (int i = 0; i < 2; i++) {
                #pragma unroll
                for (int jp = 0; jp < 4; jp++) {
                    mma_tf32(acc[i][2 * jp + 0], af[i],
                             __float_as_uint(bv[jp].x), __float_as_uint(bv[jp].y));
                    mma_tf32(acc[i][2 * jp + 1], af[i],
                             __float_as_uint(bv[jp].z), __float_as_uint(bv[jp].w));
                }
            }
        }
        __syncthreads();
    }

    // epilogue: + bias; fp32 -> C, fp16 -> g_scratch_h
    #pragma unroll
    for (int i = 0; i < 2; i++) {
        int r0 = bm + wm + i * 16 + grp;
        #pragma unroll
        for (int j = 0; j < 8; j++) {
            int col = bn + wn + j * 8 + 2 * qd;
            float b0 = bias[col], b1 = bias[col + 1];
            float x0 = acc[i][j][0] + b0, x1 = acc[i][j][1] + b1;
            float x2 = acc[i][j][2] + b0, x3 = acc[i][j][3] + b1;
            if (r0 < N) {
                size_t off = (size_t)r0 * DOUT + col;
                *reinterpret_cast<float2*>(C + off) = make_float2(x0, x1);
                *reinterpret_cast<__half2*>(g_scratch_h + off) = __floats2half2_rn(x0, x1);
            }
            int r1 = r0 + 8;
            if (r1 < N) {
                size_t off = (size_t)r1 * DOUT + col;
                *reinterpret_cast<float2*>(C + off) = make_float2(x2, x3);
                *reinterpret_cast<__half2*>(g_scratch_h + off) = __floats2half2_rn(x2, x3);
            }
        }
    }
}

// ---------------------------------------------------------------------------
// Index loader robust to int64-vs-int32 storage.
// ---------------------------------------------------------------------------
__device__ __forceinline__ long long load_index(const void* p, long long i, bool is64)
{
    if (is64) return reinterpret_cast<const long long*>(p)[i];
    return (long long)reinterpret_cast<const int*>(p)[i];
}

// ---------------------------------------------------------------------------
// Kernel 2: aggregation + leakyrelu + in-place add.
// Neighbors: fp16 gather from g_scratch_h. Src row: fp32 from d_out (only this
// block writes that row, and it reads before writing -> race-free).
// 4 src rows per 256-thread block; 64 threads x 4 cols per row.
// ---------------------------------------------------------------------------
__global__ __launch_bounds__(256) void agg_kernel(
    const void* __restrict__ src_idx,
    const void* __restrict__ neighs,
    const float* __restrict__ mask,   // [S, K]
    float* __restrict__ out,          // [N, DOUT]
    int S, int K)
{
    __shared__ int   s_nn[4][16];
    __shared__ float s_mm[4][16];
    __shared__ int   s_src[4];

    const int grp  = threadIdx.x >> 6;   // 0..3 : src within block
    const int lane = threadIdx.x & 63;   // 0..63: 4-col group within row
    const int s    = blockIdx.x * 4 + grp;

    // dtype sniff: int64 data has zero high words (indices < 2^31);
    // int32 data puts random indices there.
    const int* ni = reinterpret_cast<const int*>(neighs);
    const bool is64 = ((ni[1] | ni[3] | ni[5] | ni[7]) == 0);

    if (s < S) {
        if (lane < 16 && lane < K) {
            s_nn[grp][lane] = (int)load_index(neighs, (long long)s * K + lane, is64);
            s_mm[grp][lane] = mask[s * K + lane];
        }
        if (lane == 0)
            s_src[grp] = (int)load_index(src_idx, s, is64);
    }
    __syncthreads();
    if (s >= S) return;

    const uint2* nb = reinterpret_cast<const uint2*>(g_scratch_h);  // 64 x 8B per row
    const int src = s_src[grp];

    float4 sv  = reinterpret_cast<const float4*>(out)[(size_t)src * 64 + lane];
    float4 acc = make_float4(0.f, 0.f, 0.f, 0.f);

    if (K == 16) {
        #pragma unroll
        for (int k = 0; k < 16; k++) {
            const int   n = s_nn[grp][k];
            const float m = s_mm[grp][k];
            uint2 q = nb[(size_t)n * 64 + lane];
            float2 f0 = __half22float2(*reinterpret_cast<__half2*>(&q.x));
            float2 f1 = __half22float2(*reinterpret_cast<__half2*>(&q.y));
            acc.x += m * f0.x; acc.y += m * f0.y;
            acc.z += m * f1.x; acc.w += m * f1.y;
        }
    } else {
        for (int k = 0; k < K; k++) {
            long long n = load_index(neighs, (long long)s * K + k, is64);
            float     m = mask[s * K + k];
            uint2 q = nb[(size_t)n * 64 + lane];
            float2 f0 = __half22float2(*reinterpret_cast<__half2*>(&q.x));
            float2 f1 = __half22float2(*reinterpret_cast<__half2*>(&q.y));
            acc.x += m * f0.x; acc.y += m * f0.y;
            acc.z += m * f1.x; acc.w += m * f1.y;
        }
    }

    float4 t;
    t.x = acc.x + sv.x; t.y = acc.y + sv.y;
    t.z = acc.z + sv.z; t.w = acc.w + sv.w;
    t.x = (t.x >= 0.f) ? t.x : 0.2f * t.x;
    t.y = (t.y >= 0.f) ? t.y : 0.2f * t.y;
    t.z = (t.z >= 0.f) ? t.z : 0.2f * t.z;
    t.w = (t.w >= 0.f) ? t.w : 0.2f * t.w;

    float4 o;
    o.x = sv.x + t.x; o.y = sv.y + t.y;
    o.z = sv.z + t.z; o.w = sv.w + t.w;

    reinterpret_cast<float4*>(out)[(size_t)src * 64 + lane] = o;
}

// ---------------------------------------------------------------------------
// Inputs (metadata order):
//   0 word_vectors [N,DIN] f32, 1 src_idx [S] int, 2 neighs_idx [S,K] int,
//   3 src_mask [S,K] f32, 4 W [DOUT,DIN] f32, 5 b [DOUT] f32
// ---------------------------------------------------------------------------
extern "C" void kernel_launch(void* const* d_in, const int* in_sizes, int n_in,
                              void* d_out, int out_size)
{
    const float* wv    = (const float*)d_in[0];
    const void*  srcix = d_in[1];
    const void*  neigh = d_in[2];
    const float* mask  = (const float*)d_in[3];
    const float* W     = (const float*)d_in[4];
    const float* bias  = (const float*)d_in[5];
    float*       out   = (float*)d_out;

    const int dout = in_sizes[5];          // 256
    const int din  = in_sizes[4] / dout;   // 256
    const int N    = in_sizes[0] / din;    // 100000
    const int S    = in_sizes[1];          // 50000
    const int K    = in_sizes[3] / S;      // 16
    (void)n_in; (void)out_size; (void)din;

    dim3 ggrid((N + BM - 1) / BM, DOUT / BN);
    gemm_tc<<<ggrid, 256>>>(wv, W, bias, out, N);

    agg_kernel<<<(S + 3) / 4, 256>>>(srcix, neigh, mask, out, S, K);
}